// round 9
// baseline (speedup 1.0000x reference)
#include <cuda_runtime.h>
#include <cstdint>

// Problem constants: N=4096, L_V=64, H=512, D=256
constexpr int NB   = 4096;
constexpr int LV   = 64;
constexpr int HD   = 512;
constexpr int DD   = 256;
constexpr int K1   = 3 * DD;   // 768
constexpr int KTOT = K1 + HD;  // 1280

// GEMM tiling
constexpr int BM = 128, BN = 128, BK = 16;
constexpr int TM = 8,   TN = 8;
constexpr int NIT    = KTOT / BK;  // 80
constexpr int NSTAGE = 3;          // 3-stage cp.async pipeline
constexpr int GEMM_CTAS  = (NB / BM) * (HD / BN);  // 128
constexpr int TOTAL_CTAS = 304;                    // 2 per SM on 152 SMs

// Bulk (TMA) copy pool: 8KB chunks over the 512MB passthrough
constexpr int       CHUNK   = 8192;
constexpr long long TOTAL_BYTES = (long long)NB * LV * HD * 4;   // 512MB
constexpr int       NCHUNKS = (int)(TOTAL_BYTES / CHUNK);        // 65536
constexpr int       NBUF    = 4;   // 4 x 8KB buffers per CTA

// Shared scratch union:
//   GEMM: As2 3x8KB @ [0,24K) + Bs 3x8KB @ [24K,48K)
//   Copy: 4x8KB buffers @ [0,32K) + mbarriers @ [32K,32K+32)
constexpr int SMEM_BYTES = 49152;  // 48KB static

__device__ int   g_copy_ctr;                 // zero-init at module load
__device__ float g_stage[NB * HD];           // dense next_h staging (8MB)

// ---------------- PTX helpers ----------------
__device__ __forceinline__ uint32_t s2u(const void* p) {
    uint32_t a;
    asm("{ .reg .u64 t; cvta.to.shared.u64 t, %1; cvt.u32.u64 %0, t; }"
        : "=r"(a) : "l"(p));
    return a;
}
__device__ __forceinline__ void cp16(uint32_t dst, const void* src) {
    asm volatile("cp.async.cg.shared.global [%0], [%1], 16;" :: "r"(dst), "l"(src));
}
__device__ __forceinline__ void cp_commit() {
    asm volatile("cp.async.commit_group;");
}
template <int N>
__device__ __forceinline__ void cp_wait() {
    asm volatile("cp.async.wait_group %0;" :: "n"(N));
}
__device__ __forceinline__ unsigned long long dup2(float v) {
    unsigned long long r;
    asm("mov.b64 %0, {%1, %1};" : "=l"(r) : "f"(v));
    return r;
}
__device__ __forceinline__ void ffma2(unsigned long long& d,
                                      unsigned long long a,
                                      unsigned long long b) {
    asm("fma.rn.f32x2 %0, %1, %2, %0;" : "+l"(d) : "l"(a), "l"(b));
}
__device__ __forceinline__ void unpack2(unsigned long long v, float& lo, float& hi) {
    asm("mov.b64 {%0, %1}, %2;" : "=f"(lo), "=f"(hi) : "l"(v));
}
// ---- bulk-async (TMA) 1D helpers ----
__device__ __forceinline__ void mbar_init(uint32_t mbar, uint32_t cnt) {
    asm volatile("mbarrier.init.shared.b64 [%0], %1;" :: "r"(mbar), "r"(cnt) : "memory");
}
__device__ __forceinline__ void mbar_expect(uint32_t mbar, uint32_t bytes) {
    asm volatile("mbarrier.arrive.expect_tx.shared.b64 _, [%0], %1;"
                 :: "r"(mbar), "r"(bytes) : "memory");
}
__device__ __forceinline__ void mbar_wait(uint32_t mbar, uint32_t parity) {
    asm volatile(
        "{\n\t.reg .pred P;\n\t"
        "WAIT_%=:\n\t"
        "mbarrier.try_wait.parity.acquire.cta.shared::cta.b64 P, [%0], %1, 0x989680;\n\t"
        "@P bra.uni DONE_%=;\n\t"
        "bra.uni WAIT_%=;\n\t"
        "DONE_%=:\n\t}"
        :: "r"(mbar), "r"(parity) : "memory");
}
__device__ __forceinline__ void bulk_load(uint32_t dst, const void* src,
                                          uint32_t bytes, uint32_t mbar) {
    asm volatile(
        "cp.async.bulk.shared::cluster.global.mbarrier::complete_tx::bytes "
        "[%0], [%1], %2, [%3];"
        :: "r"(dst), "l"(src), "r"(bytes), "r"(mbar) : "memory");
}
__device__ __forceinline__ void bulk_store(void* dst, uint32_t src, uint32_t bytes) {
    asm volatile("cp.async.bulk.global.shared::cta.bulk_group [%0], [%1], %2;"
                 :: "l"(dst), "r"(src), "r"(bytes) : "memory");
}
__device__ __forceinline__ void bulk_commit() {
    asm volatile("cp.async.bulk.commit_group;");
}
template <int N>
__device__ __forceinline__ void bulk_wait_read() {
    asm volatile("cp.async.bulk.wait_group.read %0;" :: "n"(N) : "memory");
}
template <int N>
__device__ __forceinline__ void bulk_wait() {
    asm volatile("cp.async.bulk.wait_group %0;" :: "n"(N) : "memory");
}
__device__ __forceinline__ void fence_proxy() {
    asm volatile("fence.proxy.async.shared::cta;" ::: "memory");
}

// --------------------------------------------------------------------------
// Copy role (single thread per CTA): 4-deep bulk-async bounce pipeline.
// Work-stealing 8KB chunks: gmem -> smem (mbarrier) -> gmem (bulk_group).
// Only serialization per chunk is wait_group.read<0> (smem-read of the just-
// issued store, ~150-300cyc) before reusing that buffer for the next load.
// --------------------------------------------------------------------------
__device__ void copy_role_tma(char* raw, const char* __restrict__ src,
                              char* __restrict__ dst)
{
    const uint32_t base = s2u(raw);
    const uint32_t mbb  = base + NBUF * CHUNK;   // mbarriers at +32KB

    int      chunk[NBUF];
    uint32_t ph[NBUF];
    #pragma unroll
    for (int b = 0; b < NBUF; b++) { mbar_init(mbb + 8 * b, 1); ph[b] = 0; }
    fence_proxy();

    #pragma unroll
    for (int b = 0; b < NBUF; b++) {
        int c = atomicAdd(&g_copy_ctr, 1);
        chunk[b] = (c < NCHUNKS) ? c : -1;
        if (chunk[b] >= 0) {
            mbar_expect(mbb + 8 * b, CHUNK);
            bulk_load(base + b * CHUNK, src + (size_t)c * CHUNK, CHUNK, mbb + 8 * b);
        }
    }

    int b = 0;
    while (chunk[b] >= 0) {
        mbar_wait(mbb + 8 * b, ph[b]);
        ph[b] ^= 1;
        bulk_store(dst + (size_t)chunk[b] * CHUNK, base + b * CHUNK, CHUNK);
        bulk_commit();

        int c = atomicAdd(&g_copy_ctr, 1);
        if (c < NCHUNKS) {
            bulk_wait_read<0>();          // this buffer's store has read smem
            mbar_expect(mbb + 8 * b, CHUNK);
            bulk_load(base + b * CHUNK, src + (size_t)c * CHUNK, CHUNK, mbb + 8 * b);
            chunk[b] = c;
        } else {
            chunk[b] = -1;               // remaining buffers drain on later laps
        }
        b = (b + 1) & (NBUF - 1);
    }
    bulk_wait<0>();                       // all stores fully complete
}

// --------------------------------------------------------------------------
// Fused kernel. bids [0,128): one 128x128 tile of
//   tanh(X@W_in + cur_h@W_h + b) written DENSELY to g_stage (scatter kernel
// places it afterwards). 3-stage cp.async pipeline, FFMA2 math.
// Thread 0 of every CTA ends in (copy-only CTAs start in) the TMA copy pool.
// --------------------------------------------------------------------------
__global__ __launch_bounds__(256, 2)
void fused_kernel(const float* __restrict__ memory,
                  const int*   __restrict__ veh_idx,
                  const float* __restrict__ veh_repr,
                  const float* __restrict__ cust_repr,
                  const float* __restrict__ edge_emb,
                  const float* __restrict__ W_in,
                  const float* __restrict__ b_in,
                  const float* __restrict__ W_h,
                  const float* __restrict__ b_h,
                  float* __restrict__ out)
{
    __shared__ __align__(1024) char raw[SMEM_BYTES];

    const int tid = threadIdx.x;
    const int bid = blockIdx.x;

    if (bid < GEMM_CTAS) {
        float (*As2)[BM][BK] = (float (*)[BM][BK])(raw);                    // 24KB
        float (*Bs)[BK][BN]  = (float (*)[BK][BN])(raw + NSTAGE * BM * BK * 4);

        const int block_m = (bid >> 2) * BM;
        const int block_n = (bid & 3) * BN;

        // A cp.async mapping: 512 16B-chunks = 128 m x 4 k-chunks; 2/thread
        const int m0  = tid >> 2;
        const int kc  = (tid & 3) * 4;
        const int gm0 = block_m + m0;
        const int gm1 = gm0 + 64;
        const int idx0 = veh_idx[gm0] & (LV - 1);
        const int idx1 = veh_idx[gm1] & (LV - 1);
        const size_t memrow0 = ((size_t)gm0 * LV + idx0) * HD;
        const size_t memrow1 = ((size_t)gm1 * LV + idx1) * HD;
        const uint32_t aDst0 = s2u(&As2[0][m0][kc]);
        const uint32_t aDst1 = s2u(&As2[0][m0 + 64][kc]);

        // B cp.async mapping: 512 chunks = 16 k x 32 n-chunks; 2/thread
        const int kb = tid >> 5;
        const int nc = (tid & 31) * 4;
        const uint32_t bDst0 = s2u(&Bs[0][kb][nc]);
        const uint32_t bDst1 = s2u(&Bs[0][kb + 8][nc]);

        constexpr uint32_t A_STAGE = BM * BK * 4;   // 8192
        constexpr uint32_t B_STAGE = BK * BN * 4;   // 8192

        auto issue_tile = [&](int it, int buf) {
            const int k0 = it * BK;
            const uint32_t aoff = (uint32_t)buf * A_STAGE;
            const uint32_t boff = (uint32_t)buf * B_STAGE;
            const float *s0, *s1;
            if (k0 < DD) {
                s0 = veh_repr + (size_t)gm0 * DD + k0 + kc;
                s1 = veh_repr + (size_t)gm1 * DD + k0 + kc;
            } else if (k0 < 2 * DD) {
                const int o = k0 - DD;
                s0 = cust_repr + (size_t)gm0 * DD + o + kc;
                s1 = cust_repr + (size_t)gm1 * DD + o + kc;
            } else if (k0 < K1) {
                const int o = k0 - 2 * DD;
                s0 = edge_emb + (size_t)gm0 * DD + o + kc;
                s1 = edge_emb + (size_t)gm1 * DD + o + kc;
            } else {
                const int o = k0 - K1;
                s0 = memory + memrow0 + o + kc;
                s1 = memory + memrow1 + o + kc;
            }
            cp16(aDst0 + aoff, s0);
            cp16(aDst1 + aoff, s1);

            const int gk0 = k0 + kb;
            const int gk1 = gk0 + 8;
            const float* w0 = (gk0 < K1) ? (W_in + (size_t)gk0 * HD)
                                         : (W_h + (size_t)(gk0 - K1) * HD);
            const float* w1 = (gk1 < K1) ? (W_in + (size_t)gk1 * HD)
                                         : (W_h + (size_t)(gk1 - K1) * HD);
            cp16(bDst0 + boff, w0 + block_n + nc);
            cp16(bDst1 + boff, w1 + block_n + nc);
            cp_commit();
        };

        const int tm = (tid >> 4) * TM;
        const int tn = (tid & 15) * TN;

        unsigned long long acc[TM][TN / 2];
        #pragma unroll
        for (int i = 0; i < TM; i++)
            #pragma unroll
            for (int j = 0; j < TN / 2; j++) acc[i][j] = 0ull;

        issue_tile(0, 0);
        issue_tile(1, 1);

        int buf = 0, nbuf = 2;   // nbuf = (it+2) % 3
        for (int it = 0; it < NIT; it++) {
            if (it + 2 < NIT) cp_wait<1>(); else cp_wait<0>();
            __syncthreads();
            if (it + 2 < NIT) issue_tile(it + 2, nbuf);

            #pragma unroll
            for (int k2 = 0; k2 < BK / 2; k2++) {
                float2 a01[TM];
                #pragma unroll
                for (int i = 0; i < TM; i++)
                    a01[i] = *(const float2*)&As2[buf][tm + i][2 * k2];

                ulonglong2 B00 = *(const ulonglong2*)&Bs[buf][2 * k2][tn];
                ulonglong2 B01 = *(const ulonglong2*)&Bs[buf][2 * k2][tn + 4];
                ulonglong2 B10 = *(const ulonglong2*)&Bs[buf][2 * k2 + 1][tn];
                ulonglong2 B11 = *(const ulonglong2*)&Bs[buf][2 * k2 + 1][tn + 4];
                unsigned long long b0[4] = {B00.x, B00.y, B01.x, B01.y};
                unsigned long long b1[4] = {B10.x, B10.y, B11.x, B11.y};

                #pragma unroll
                for (int i = 0; i < TM; i++) {
                    const unsigned long long a0 = dup2(a01[i].x);
                    const unsigned long long a1 = dup2(a01[i].y);
                    #pragma unroll
                    for (int j = 0; j < 4; j++) {
                        ffma2(acc[i][j], a0, b0[j]);
                        ffma2(acc[i][j], a1, b1[j]);
                    }
                }
            }
            buf  = (buf  == 2) ? 0 : buf + 1;
            nbuf = (nbuf == 2) ? 0 : nbuf + 1;
        }

        // epilogue: unpack + bias + tanh -> DENSE staging (no scatter here)
        float bias[TN];
        #pragma unroll
        for (int j = 0; j < TN; j++) {
            const int n = block_n + tn + j;
            bias[j] = b_in[n] + b_h[n];
        }
        #pragma unroll
        for (int i = 0; i < TM; i++) {
            const int gm = block_m + tm + i;
            float* dst = &g_stage[(size_t)gm * HD + block_n + tn];
            float o[TN];
            #pragma unroll
            for (int j = 0; j < 4; j++)
                unpack2(acc[i][j], o[2 * j], o[2 * j + 1]);
            float4 o0, o1;
            o0.x = tanhf(o[0] + bias[0]);
            o0.y = tanhf(o[1] + bias[1]);
            o0.z = tanhf(o[2] + bias[2]);
            o0.w = tanhf(o[3] + bias[3]);
            o1.x = tanhf(o[4] + bias[4]);
            o1.y = tanhf(o[5] + bias[5]);
            o1.z = tanhf(o[6] + bias[6]);
            o1.w = tanhf(o[7] + bias[7]);
            *(float4*)&dst[0] = o0;
            *(float4*)&dst[4] = o1;
        }
        __syncthreads();   // all warps done with smem before thread 0 reuses it
    }

    if (tid != 0) return;   // copy role is single-threaded per CTA
    copy_role_tma(raw, (const char*)memory, (char*)out);
}

// --------------------------------------------------------------------------
// Scatter kernel: out[n, veh_idx[n], :] = g_stage[n, :]; resets counter.
// --------------------------------------------------------------------------
__global__ __launch_bounds__(128)
void scatter_kernel(const int* __restrict__ veh_idx, float* __restrict__ out)
{
    if (blockIdx.x == 0 && threadIdx.x == 0) g_copy_ctr = 0;
    const int n   = blockIdx.x;
    const int idx = veh_idx[n] & (LV - 1);
    const float4* s = (const float4*)&g_stage[(size_t)n * HD];
    float4*       d = (float4*)&out[((size_t)n * LV + idx) * HD];
    d[threadIdx.x] = s[threadIdx.x];
}

extern "C" void kernel_launch(void* const* d_in, const int* in_sizes, int n_in,
                              void* d_out, int out_size)
{
    const float* memory    = (const float*)d_in[0];
    const int*   veh_idx   = (const int*)d_in[1];
    const float* veh_repr  = (const float*)d_in[2];
    const float* cust_repr = (const float*)d_in[3];
    const float* edge_emb  = (const float*)d_in[4];
    const float* W_in      = (const float*)d_in[5];
    const float* b_in      = (const float*)d_in[6];
    const float* W_h       = (const float*)d_in[7];
    const float* b_h       = (const float*)d_in[8];
    float*       out       = (float*)d_out;

    fused_kernel<<<TOTAL_CTAS, 256>>>(memory, veh_idx, veh_repr, cust_repr,
                                      edge_emb, W_in, b_in, W_h, b_h, out);
    scatter_kernel<<<NB, 128>>>(veh_idx, out);
}

// round 10
// speedup vs baseline: 1.4539x; 1.4539x over previous
#include <cuda_runtime.h>
#include <cuda_bf16.h>
#include <cstdint>

// Problem constants: N=4096, L_V=64, H=512, D=256
constexpr int NB   = 4096;
constexpr int LV   = 64;
constexpr int HD   = 512;
constexpr int DD   = 256;
constexpr int K1   = 3 * DD;   // 768
constexpr int KTOT = K1 + HD;  // 1280

// GEMM tiling: CTA tile 128x128, K stepped by 16 (one m16n8k16 per step)
constexpr int BM = 128, BN = 128, BKS = 16;
constexpr int NIT = KTOT / BKS;                    // 80
constexpr int GEMM_CTAS  = (NB / BM) * (HD / BN);  // 128
constexpr int TOTAL_CTAS = 304;                    // 2 per SM on 152 SMs

// Copy pool
constexpr int ROWS_TOTAL = NB * LV;                // 262144 rows of 512 floats
constexpr int NUM_GRABS  = ROWS_TOTAL / 32;        // 8192

// prep kernel block split
constexpr int XCHUNKS = NB * KTOT / 4;             // 1,310,720 float4s
constexpr int XBLOCKS = XCHUNKS / 256;             // 5120
constexpr int WCHUNKS = HD * KTOT / 4;             // 163,840
constexpr int WBLOCKS = WCHUNKS / 256;             // 640

__device__ int   g_copy_ctr;                       // zero-init; prep resets
__device__ float g_stage[NB * HD];                 // dense next_h (8MB)
__device__ __align__(16) __nv_bfloat16 g_xhi[NB * KTOT];  // X hi plane (10MB)
__device__ __align__(16) __nv_bfloat16 g_xlo[NB * KTOT];  // X lo plane
__device__ __align__(16) __nv_bfloat16 g_whi[HD * KTOT];  // W^T hi (k-major)
__device__ __align__(16) __nv_bfloat16 g_wlo[HD * KTOT];  // W^T lo

// ---------------- PTX helpers ----------------
__device__ __forceinline__ uint32_t s2u(const void* p) {
    uint32_t a;
    asm("{ .reg .u64 t; cvta.to.shared.u64 t, %1; cvt.u32.u64 %0, t; }"
        : "=r"(a) : "l"(p));
    return a;
}
__device__ __forceinline__ void cp16(uint32_t dst, const void* src) {
    asm volatile("cp.async.cg.shared.global [%0], [%1], 16;" :: "r"(dst), "l"(src));
}
__device__ __forceinline__ void cp_commit() {
    asm volatile("cp.async.commit_group;");
}
template <int N>
__device__ __forceinline__ void cp_wait() {
    asm volatile("cp.async.wait_group %0;" :: "n"(N));
}
__device__ __forceinline__ void ldsm4(uint32_t* r, uint32_t addr) {
    asm volatile("ldmatrix.sync.aligned.m8n8.x4.shared.b16 {%0,%1,%2,%3}, [%4];"
                 : "=r"(r[0]), "=r"(r[1]), "=r"(r[2]), "=r"(r[3]) : "r"(addr));
}
__device__ __forceinline__ void mma16816(float* d, const uint32_t* a,
                                         const uint32_t* b) {
    asm volatile(
        "mma.sync.aligned.m16n8k16.row.col.f32.bf16.bf16.f32 "
        "{%0,%1,%2,%3}, {%4,%5,%6,%7}, {%8,%9}, {%0,%1,%2,%3};"
        : "+f"(d[0]), "+f"(d[1]), "+f"(d[2]), "+f"(d[3])
        : "r"(a[0]), "r"(a[1]), "r"(a[2]), "r"(a[3]), "r"(b[0]), "r"(b[1]));
}
__device__ __forceinline__ float4 ldcs(const float4* p) {
    float4 v;
    asm volatile("ld.global.cs.v4.f32 {%0,%1,%2,%3}, [%4];"
                 : "=f"(v.x), "=f"(v.y), "=f"(v.z), "=f"(v.w) : "l"(p));
    return v;
}
__device__ __forceinline__ void stcs(float4* p, float4 v) {
    asm volatile("st.global.cs.v4.f32 [%0], {%1,%2,%3,%4};"
                 :: "l"(p), "f"(v.x), "f"(v.y), "f"(v.z), "f"(v.w) : "memory");
}

// --------------------------------------------------------------------------
// prep kernel: (a) X = concat(veh,cust,edge,cur_h) -> bf16 hi/lo planes,
// (b) W^T (k-major) -> bf16 hi/lo planes, (c) reset copy counter.
// --------------------------------------------------------------------------
__global__ __launch_bounds__(256)
void prep_kernel(const float* __restrict__ memory,
                 const int*   __restrict__ veh_idx,
                 const float* __restrict__ veh_repr,
                 const float* __restrict__ cust_repr,
                 const float* __restrict__ edge_emb,
                 const float* __restrict__ W_in,
                 const float* __restrict__ W_h)
{
    if (blockIdx.x == 0 && threadIdx.x == 0) g_copy_ctr = 0;
    const int cid = blockIdx.x * 256 + threadIdx.x;

    if (blockIdx.x < XBLOCKS) {
        const int e = cid * 4;
        const int m = e / KTOT;
        const int k = e % KTOT;
        const float* src;
        if (k < DD)            src = veh_repr  + (size_t)m * DD + k;
        else if (k < 2 * DD)   src = cust_repr + (size_t)m * DD + (k - DD);
        else if (k < K1)       src = edge_emb  + (size_t)m * DD + (k - 2 * DD);
        else {
            const int idx = veh_idx[m] & (LV - 1);
            src = memory + ((size_t)m * LV + idx) * HD + (k - K1);
        }
        const float4 v = *(const float4*)src;
        const float xs[4] = {v.x, v.y, v.z, v.w};
        __nv_bfloat16 h[4], l[4];
        #pragma unroll
        for (int t = 0; t < 4; t++) {
            h[t] = __float2bfloat16_rn(xs[t]);
            l[t] = __float2bfloat16_rn(xs[t] - __bfloat162float(h[t]));
        }
        uint2 ph, pl;
        ph.x = ((uint32_t)*(uint16_t*)&h[1] << 16) | *(uint16_t*)&h[0];
        ph.y = ((uint32_t)*(uint16_t*)&h[3] << 16) | *(uint16_t*)&h[2];
        pl.x = ((uint32_t)*(uint16_t*)&l[1] << 16) | *(uint16_t*)&l[0];
        pl.y = ((uint32_t)*(uint16_t*)&l[3] << 16) | *(uint16_t*)&l[2];
        *(uint2*)&g_xhi[e] = ph;
        *(uint2*)&g_xlo[e] = pl;
    } else {
        const int c = cid - XBLOCKS * 256;
        const int e = c * 4;                   // linear index into WT[n][k]
        const int n = e / KTOT;
        const int k = e % KTOT;
        float ws[4];
        #pragma unroll
        for (int t = 0; t < 4; t++) {
            const int kk = k + t;
            ws[t] = (kk < K1) ? W_in[(size_t)kk * HD + n]
                              : W_h[(size_t)(kk - K1) * HD + n];
        }
        __nv_bfloat16 h[4], l[4];
        #pragma unroll
        for (int t = 0; t < 4; t++) {
            h[t] = __float2bfloat16_rn(ws[t]);
            l[t] = __float2bfloat16_rn(ws[t] - __bfloat162float(h[t]));
        }
        uint2 ph, pl;
        ph.x = ((uint32_t)*(uint16_t*)&h[1] << 16) | *(uint16_t*)&h[0];
        ph.y = ((uint32_t)*(uint16_t*)&h[3] << 16) | *(uint16_t*)&h[2];
        pl.x = ((uint32_t)*(uint16_t*)&l[1] << 16) | *(uint16_t*)&l[0];
        pl.y = ((uint32_t)*(uint16_t*)&l[3] << 16) | *(uint16_t*)&l[2];
        *(uint2*)&g_whi[e] = ph;
        *(uint2*)&g_wlo[e] = pl;
    }
}

// --------------------------------------------------------------------------
// Copy role: work-stealing passthrough (no skip — scatter overwrites later).
// Warp grabs 32 rows; 4 rows per group with 16 LDG.128 in flight. .cs hints.
// --------------------------------------------------------------------------
__device__ __forceinline__ void copy_role(const float4* __restrict__ src,
                                          float4* __restrict__ dst, int lane)
{
    for (;;) {
        int c;
        if (lane == 0) c = atomicAdd(&g_copy_ctr, 1);
        c = __shfl_sync(0xffffffffu, c, 0);
        if (c >= NUM_GRABS) return;

        const int r0 = c * 32;
        for (int g = 0; g < 8; g++) {
            float4 v[16];
            size_t base = (size_t)(r0 + g * 4) * (HD / 4) + lane;
            #pragma unroll
            for (int rr = 0; rr < 4; rr++)
                #pragma unroll
                for (int q = 0; q < 4; q++)
                    v[rr * 4 + q] = ldcs(src + base + rr * 128 + q * 32);
            #pragma unroll
            for (int rr = 0; rr < 4; rr++)
                #pragma unroll
                for (int q = 0; q < 4; q++)
                    stcs(dst + base + rr * 128 + q * 32, v[rr * 4 + q]);
        }
    }
}

// --------------------------------------------------------------------------
// Fused kernel. bids [0,128): tensor-core GEMM tile via mma.sync bf16 with
// 3-term hi/lo split (full ~1e-5 accuracy), 3-stage cp.async pipeline.
// tanh(acc + bias) -> dense g_stage. All CTAs end in the copy pool.
// --------------------------------------------------------------------------
__global__ __launch_bounds__(256, 2)
void fused_kernel(const float* __restrict__ memory,
                  const float* __restrict__ b_in,
                  const float* __restrict__ b_h,
                  float* __restrict__ out)
{
    // 3 stages x 16KB: per stage: xhi[128][16] | xlo | whi[128][16] | wlo
    __shared__ __align__(128) char raw[49152];

    const int tid  = threadIdx.x;
    const int bid  = blockIdx.x;
    const int lane = tid & 31;

    if (bid < GEMM_CTAS) {
        const int block_m = (bid >> 2) * BM;
        const int block_n = (bid & 3) * BN;
        const int w  = tid >> 5;
        const int wm = w >> 1;          // 0..3 -> rows wm*32
        const int wn = w & 1;           // 0..1 -> cols wn*64
        const uint32_t sbase = s2u(raw);

        // cp.async mapping: thread -> (row 0..127, 16B half)
        const int row  = tid >> 1;
        const int half = tid & 1;
        const uint32_t dxy = (uint32_t)(row * 32 + half * 16);
        const size_t gx = (size_t)(block_m + row) * KTOT + half * 8;
        const size_t gw = (size_t)(block_n + row) * KTOT + half * 8;

        auto issue = [&](int it, int buf) {
            const int k0 = it * BKS;
            const uint32_t sb = sbase + (uint32_t)buf * 16384;
            cp16(sb + dxy,          g_xhi + gx + k0);
            cp16(sb + 4096 + dxy,   g_xlo + gx + k0);
            cp16(sb + 8192 + dxy,   g_whi + gw + k0);
            cp16(sb + 12288 + dxy,  g_wlo + gw + k0);
            cp_commit();
        };

        // ldmatrix lane offsets (bytes within a stage sub-array)
        // A fragment (m16k16), m-tile i: matrices [r0-7 k0-7][r8-15 k0-7][r0-7 k8-15][r8-15 k8-15]
        uint32_t aoff[2];
        #pragma unroll
        for (int i = 0; i < 2; i++) {
            const int r = wm * 32 + i * 16 + (lane & 7) + ((lane >> 3) & 1) * 8;
            aoff[i] = (uint32_t)(r * 32 + ((lane >> 4) & 1) * 16);
        }
        // B fragments (k16n8), pair p covers n-tiles 2p,2p+1:
        // matrices [t2p k0-7][t2p k8-15][t2p+1 k0-7][t2p+1 k8-15]
        uint32_t boff[4];
        #pragma unroll
        for (int p = 0; p < 4; p++) {
            const int r = wn * 64 + p * 16 + (lane & 7) + ((lane >> 4) & 1) * 8;
            boff[p] = (uint32_t)(r * 32 + ((lane >> 3) & 1) * 16);
        }

        float d[2][8][4];
        #pragma unroll
        for (int i = 0; i < 2; i++)
            #pragma unroll
            for (int j = 0; j < 8; j++)
                #pragma unroll
                for (int q = 0; q < 4; q++) d[i][j][q] = 0.0f;

        issue(0, 0);
        issue(1, 1);

        int buf = 0, nbuf = 2;
        for (int it = 0; it < NIT; it++) {
            if (it + 2 < NIT) cp_wait<1>(); else cp_wait<0>();
            __syncthreads();
            if (it + 2 < NIT) issue(it + 2, nbuf);

            const uint32_t sb = sbase + (uint32_t)buf * 16384;
            uint32_t ah[2][4], al[2][4], bb[8][2];
            ldsm4(ah[0], sb + aoff[0]);
            ldsm4(ah[1], sb + aoff[1]);
            ldsm4(al[0], sb + 4096 + aoff[0]);
            ldsm4(al[1], sb + 4096 + aoff[1]);
            #pragma unroll
            for (int p = 0; p < 4; p++) {
                uint32_t r[4];
                ldsm4(r, sb + 8192 + boff[p]);      // W hi
                bb[2 * p][0] = r[0]; bb[2 * p][1] = r[1];
                bb[2 * p + 1][0] = r[2]; bb[2 * p + 1][1] = r[3];
            }
            #pragma unroll
            for (int i = 0; i < 2; i++)
                #pragma unroll
                for (int j = 0; j < 8; j++) {
                    mma16816(d[i][j], ah[i], bb[j]);   // hi*hi
                    mma16816(d[i][j], al[i], bb[j]);   // lo*hi
                }
            #pragma unroll
            for (int p = 0; p < 4; p++) {
                uint32_t r[4];
                ldsm4(r, sb + 12288 + boff[p]);     // W lo
                bb[2 * p][0] = r[0]; bb[2 * p][1] = r[1];
                bb[2 * p + 1][0] = r[2]; bb[2 * p + 1][1] = r[3];
            }
            #pragma unroll
            for (int i = 0; i < 2; i++)
                #pragma unroll
                for (int j = 0; j < 8; j++)
                    mma16816(d[i][j], ah[i], bb[j]);   // hi*lo

            buf  = (buf  == 2) ? 0 : buf + 1;
            nbuf = (nbuf == 2) ? 0 : nbuf + 1;
        }

        // epilogue: bias + tanh -> dense g_stage
        float2 bias[8];
        #pragma unroll
        for (int j = 0; j < 8; j++) {
            const int col = block_n + wn * 64 + j * 8 + (lane & 3) * 2;
            bias[j].x = b_in[col] + b_h[col];
            bias[j].y = b_in[col + 1] + b_h[col + 1];
        }
        #pragma unroll
        for (int i = 0; i < 2; i++) {
            const int r0 = block_m + wm * 32 + i * 16 + (lane >> 2);
            #pragma unroll
            for (int j = 0; j < 8; j++) {
                const int col = block_n + wn * 64 + j * 8 + (lane & 3) * 2;
                float2 v0, v1;
                v0.x = tanhf(d[i][j][0] + bias[j].x);
                v0.y = tanhf(d[i][j][1] + bias[j].y);
                v1.x = tanhf(d[i][j][2] + bias[j].x);
                v1.y = tanhf(d[i][j][3] + bias[j].y);
                *(float2*)&g_stage[(size_t)r0 * HD + col]       = v0;
                *(float2*)&g_stage[(size_t)(r0 + 8) * HD + col] = v1;
            }
        }
    }

    // Copy pool (copy-only CTAs arrive here immediately; no smem used).
    copy_role((const float4*)memory, (float4*)out, lane);
}

// --------------------------------------------------------------------------
// Scatter kernel: out[n, veh_idx[n], :] = g_stage[n, :]
// --------------------------------------------------------------------------
__global__ __launch_bounds__(128)
void scatter_kernel(const int* __restrict__ veh_idx, float* __restrict__ out)
{
    const int n   = blockIdx.x;
    const int idx = veh_idx[n] & (LV - 1);
    const float4* s = (const float4*)&g_stage[(size_t)n * HD];
    float4*       d = (float4*)&out[((size_t)n * LV + idx) * HD];
    d[threadIdx.x] = s[threadIdx.x];
}

extern "C" void kernel_launch(void* const* d_in, const int* in_sizes, int n_in,
                              void* d_out, int out_size)
{
    const float* memory    = (const float*)d_in[0];
    const int*   veh_idx   = (const int*)d_in[1];
    const float* veh_repr  = (const float*)d_in[2];
    const float* cust_repr = (const float*)d_in[3];
    const float* edge_emb  = (const float*)d_in[4];
    const float* W_in      = (const float*)d_in[5];
    const float* b_in      = (const float*)d_in[6];
    const float* W_h       = (const float*)d_in[7];
    const float* b_h       = (const float*)d_in[8];
    float*       out       = (float*)d_out;

    prep_kernel<<<XBLOCKS + WBLOCKS, 256>>>(memory, veh_idx, veh_repr,
                                            cust_repr, edge_emb, W_in, W_h);
    fused_kernel<<<TOTAL_CTAS, 256>>>(memory, b_in, b_h, out);
    scatter_kernel<<<NB, 128>>>(veh_idx, out);
}

// round 11
// speedup vs baseline: 1.5117x; 1.0397x over previous
#include <cuda_runtime.h>
#include <cuda_bf16.h>
#include <cstdint>

// Problem constants: N=4096, L_V=64, H=512, D=256
constexpr int NB   = 4096;
constexpr int LV   = 64;
constexpr int HD   = 512;
constexpr int DD   = 256;
constexpr int K1   = 3 * DD;   // 768
constexpr int KTOT = K1 + HD;  // 1280

// GEMM tiling: CTA tile 128x128, K stepped by 16 (one m16n8k16 per step)
constexpr int BM = 128, BN = 128, BKS = 16;
constexpr int NIT = KTOT / BKS;                    // 80
constexpr int GEMM_CTAS  = (NB / BM) * (HD / BN);  // 128
constexpr int TOTAL_CTAS = 304;                    // 2 per SM on 152 SMs

// Copy pool
constexpr int ROWS_TOTAL = NB * LV;                // 262144 rows of 512 floats
constexpr int NUM_GRABS  = ROWS_TOTAL / 32;        // 8192

// prep kernel: X conversion blocks + W transpose blocks
constexpr int XCHUNKS = NB * KTOT / 4;             // 1,310,720 float4s
constexpr int XBLOCKS = XCHUNKS / 256;             // 5120
constexpr int WKT = 64, WNT = 32;                  // W transpose tile (k x n)
constexpr int WBLOCKS = (KTOT / WKT) * (HD / WNT); // 20*16 = 320

__device__ int g_copy_ctr;                         // zero-init; prep resets
__device__ __align__(16) __nv_bfloat16 g_xhi[NB * KTOT];  // X hi plane (10MB)
__device__ __align__(16) __nv_bfloat16 g_xlo[NB * KTOT];  // X lo plane
__device__ __align__(16) __nv_bfloat16 g_whi[HD * KTOT];  // W^T hi (k-major)
__device__ __align__(16) __nv_bfloat16 g_wlo[HD * KTOT];  // W^T lo

// ---------------- PTX helpers ----------------
__device__ __forceinline__ uint32_t s2u(const void* p) {
    uint32_t a;
    asm("{ .reg .u64 t; cvta.to.shared.u64 t, %1; cvt.u32.u64 %0, t; }"
        : "=r"(a) : "l"(p));
    return a;
}
__device__ __forceinline__ void cp16(uint32_t dst, const void* src) {
    asm volatile("cp.async.cg.shared.global [%0], [%1], 16;" :: "r"(dst), "l"(src));
}
__device__ __forceinline__ void cp_commit() {
    asm volatile("cp.async.commit_group;");
}
template <int N>
__device__ __forceinline__ void cp_wait() {
    asm volatile("cp.async.wait_group %0;" :: "n"(N));
}
__device__ __forceinline__ void ldsm4(uint32_t* r, uint32_t addr) {
    asm volatile("ldmatrix.sync.aligned.m8n8.x4.shared.b16 {%0,%1,%2,%3}, [%4];"
                 : "=r"(r[0]), "=r"(r[1]), "=r"(r[2]), "=r"(r[3]) : "r"(addr));
}
__device__ __forceinline__ void mma16816(float* d, const uint32_t* a,
                                         const uint32_t* b) {
    asm volatile(
        "mma.sync.aligned.m16n8k16.row.col.f32.bf16.bf16.f32 "
        "{%0,%1,%2,%3}, {%4,%5,%6,%7}, {%8,%9}, {%0,%1,%2,%3};"
        : "+f"(d[0]), "+f"(d[1]), "+f"(d[2]), "+f"(d[3])
        : "r"(a[0]), "r"(a[1]), "r"(a[2]), "r"(a[3]), "r"(b[0]), "r"(b[1]));
}
__device__ __forceinline__ float4 ldcs(const float4* p) {
    float4 v;
    asm volatile("ld.global.cs.v4.f32 {%0,%1,%2,%3}, [%4];"
                 : "=f"(v.x), "=f"(v.y), "=f"(v.z), "=f"(v.w) : "l"(p));
    return v;
}
__device__ __forceinline__ void stcs(float4* p, float4 v) {
    asm volatile("st.global.cs.v4.f32 [%0], {%1,%2,%3,%4};"
                 :: "l"(p), "f"(v.x), "f"(v.y), "f"(v.z), "f"(v.w) : "memory");
}
__device__ __forceinline__ uint32_t pack_hi2(float a, float b,
                                             float& ra, float& rb) {
    __nv_bfloat16 h0 = __float2bfloat16_rn(a);
    __nv_bfloat16 h1 = __float2bfloat16_rn(b);
    ra = a - __bfloat162float(h0);
    rb = b - __bfloat162float(h1);
    return ((uint32_t)*(uint16_t*)&h1 << 16) | *(uint16_t*)&h0;
}
__device__ __forceinline__ uint32_t pack_bf2(float a, float b) {
    __nv_bfloat162 t = __floats2bfloat162_rn(a, b);
    return *reinterpret_cast<uint32_t*>(&t);
}

// --------------------------------------------------------------------------
// prep kernel:
//  blocks [0, XBLOCKS):          X = concat(veh,cust,edge,cur_h) -> hi/lo
//  blocks [XBLOCKS, +WBLOCKS):   W^T (k-major) -> hi/lo, via smem transpose
//  block 0 thread 0 also resets the copy counter.
// --------------------------------------------------------------------------
__global__ __launch_bounds__(256)
void prep_kernel(const float* __restrict__ memory,
                 const int*   __restrict__ veh_idx,
                 const float* __restrict__ veh_repr,
                 const float* __restrict__ cust_repr,
                 const float* __restrict__ edge_emb,
                 const float* __restrict__ W_in,
                 const float* __restrict__ W_h)
{
    if (blockIdx.x == 0 && threadIdx.x == 0) g_copy_ctr = 0;
    const int tid = threadIdx.x;

    if (blockIdx.x < XBLOCKS) {
        const int e = (blockIdx.x * 256 + tid) * 4;
        const int m = e / KTOT;
        const int k = e % KTOT;
        const float* src;
        if (k < DD)            src = veh_repr  + (size_t)m * DD + k;
        else if (k < 2 * DD)   src = cust_repr + (size_t)m * DD + (k - DD);
        else if (k < K1)       src = edge_emb  + (size_t)m * DD + (k - 2 * DD);
        else {
            const int idx = veh_idx[m] & (LV - 1);
            src = memory + ((size_t)m * LV + idx) * HD + (k - K1);
        }
        const float4 v = *(const float4*)src;
        float r0, r1, r2, r3;
        uint2 ph, pl;
        ph.x = pack_hi2(v.x, v.y, r0, r1);
        ph.y = pack_hi2(v.z, v.w, r2, r3);
        pl.x = pack_bf2(r0, r1);
        pl.y = pack_bf2(r2, r3);
        *(uint2*)&g_xhi[e] = ph;
        *(uint2*)&g_xlo[e] = pl;
    } else {
        // W transpose tile: 64 k-rows x 32 n-cols, both sides coalesced
        __shared__ float tile[WKT][WNT + 1];
        const int wb    = blockIdx.x - XBLOCKS;
        const int k0    = (wb % (KTOT / WKT)) * WKT;   // multiple of 64; never
        const int n0    = (wb / (KTOT / WKT)) * WNT;   // straddles K1=768
        const float* W  = (k0 < K1) ? (W_in + (size_t)k0 * HD)
                                    : (W_h + (size_t)(k0 - K1) * HD);
        // load: 2048 elems, 8/thread, coalesced along n
        #pragma unroll
        for (int i = 0; i < 8; i++) {
            const int e = tid + i * 256;
            const int r = e >> 5;            // k row 0..63
            const int c = e & 31;            // n col 0..31
            tile[r][c] = W[(size_t)r * HD + n0 + c];
        }
        __syncthreads();
        // write: pairs along k, 4 uint32/thread, coalesced along k
        #pragma unroll
        for (int i = 0; i < 4; i++) {
            const int p  = tid + i * 256;    // pair index 0..1023
            const int n  = p >> 5;           // 0..31
            const int kk = (p & 31) * 2;     // 0..62 even
            float r0, r1;
            const uint32_t hi = pack_hi2(tile[kk][n], tile[kk + 1][n], r0, r1);
            const uint32_t lo = pack_bf2(r0, r1);
            const size_t off = (size_t)(n0 + n) * KTOT + k0 + kk;
            *(uint32_t*)&g_whi[off] = hi;
            *(uint32_t*)&g_wlo[off] = lo;
        }
    }
}

// --------------------------------------------------------------------------
// Copy role: work-stealing passthrough, skipping the row each batch's GEMM
// scatters (GEMM owns it). Warp grabs 32 rows; 4 rows per group with 16
// LDG.128 in flight. .cs hints keep the stream out of L2's hot set.
// --------------------------------------------------------------------------
__device__ __forceinline__ void copy_role(const float4* __restrict__ src,
                                          float4* __restrict__ dst,
                                          const int* __restrict__ veh_idx,
                                          int lane)
{
    for (;;) {
        int c;
        if (lane == 0) c = atomicAdd(&g_copy_ctr, 1);
        c = __shfl_sync(0xffffffffu, c, 0);
        if (c >= NUM_GRABS) return;

        const int r0   = c * 32;            // same n for the whole grab
        const int n    = r0 >> 6;
        const int skip = veh_idx[n] & (LV - 1);
        const int l0   = r0 & 63;

        for (int g = 0; g < 8; g++) {
            float4 v[16];
            size_t base = (size_t)(r0 + g * 4) * (HD / 4) + lane;
            #pragma unroll
            for (int rr = 0; rr < 4; rr++)
                #pragma unroll
                for (int q = 0; q < 4; q++)
                    v[rr * 4 + q] = ldcs(src + base + rr * 128 + q * 32);
            #pragma unroll
            for (int rr = 0; rr < 4; rr++) {
                if (l0 + g * 4 + rr == skip) continue;   // GEMM writes this row
                #pragma unroll
                for (int q = 0; q < 4; q++)
                    stcs(dst + base + rr * 128 + q * 32, v[rr * 4 + q]);
            }
        }
    }
}

// --------------------------------------------------------------------------
// Fused kernel. bids [0,128): tensor-core GEMM tile via mma.sync bf16 with
// 3-term hi/lo split, 3-stage cp.async pipeline; epilogue scatters
// tanh(acc+bias) directly into out[n, veh_idx[n], :]. All CTAs end in the
// copy pool.
// --------------------------------------------------------------------------
__global__ __launch_bounds__(256, 2)
void fused_kernel(const float* __restrict__ memory,
                  const int*   __restrict__ veh_idx,
                  const float* __restrict__ b_in,
                  const float* __restrict__ b_h,
                  float* __restrict__ out)
{
    // 3 stages x 16KB: per stage: xhi[128][16] | xlo | whi[128][16] | wlo
    __shared__ __align__(128) char raw[49152];

    const int tid  = threadIdx.x;
    const int bid  = blockIdx.x;
    const int lane = tid & 31;

    if (bid < GEMM_CTAS) {
        const int block_m = (bid >> 2) * BM;
        const int block_n = (bid & 3) * BN;
        const int w  = tid >> 5;
        const int wm = w >> 1;          // 0..3 -> rows wm*32
        const int wn = w & 1;           // 0..1 -> cols wn*64
        const uint32_t sbase = s2u(raw);

        // cp.async mapping: thread -> (row 0..127, 16B half)
        const int row  = tid >> 1;
        const int half = tid & 1;
        const uint32_t dxy = (uint32_t)(row * 32 + half * 16);
        const size_t gx = (size_t)(block_m + row) * KTOT + half * 8;
        const size_t gw = (size_t)(block_n + row) * KTOT + half * 8;

        auto issue = [&](int it, int buf) {
            const int k0 = it * BKS;
            const uint32_t sb = sbase + (uint32_t)buf * 16384;
            cp16(sb + dxy,          g_xhi + gx + k0);
            cp16(sb + 4096 + dxy,   g_xlo + gx + k0);
            cp16(sb + 8192 + dxy,   g_whi + gw + k0);
            cp16(sb + 12288 + dxy,  g_wlo + gw + k0);
            cp_commit();
        };

        // ldmatrix lane offsets
        uint32_t aoff[2];
        #pragma unroll
        for (int i = 0; i < 2; i++) {
            const int r = wm * 32 + i * 16 + (lane & 7) + ((lane >> 3) & 1) * 8;
            aoff[i] = (uint32_t)(r * 32 + ((lane >> 4) & 1) * 16);
        }
        uint32_t boff[4];
        #pragma unroll
        for (int p = 0; p < 4; p++) {
            const int r = wn * 64 + p * 16 + (lane & 7) + ((lane >> 4) & 1) * 8;
            boff[p] = (uint32_t)(r * 32 + ((lane >> 3) & 1) * 16);
        }

        float d[2][8][4];
        #pragma unroll
        for (int i = 0; i < 2; i++)
            #pragma unroll
            for (int j = 0; j < 8; j++)
                #pragma unroll
                for (int q = 0; q < 4; q++) d[i][j][q] = 0.0f;

        issue(0, 0);
        issue(1, 1);

        int buf = 0, nbuf = 2;
        for (int it = 0; it < NIT; it++) {
            if (it + 2 < NIT) cp_wait<1>(); else cp_wait<0>();
            __syncthreads();
            if (it + 2 < NIT) issue(it + 2, nbuf);

            const uint32_t sb = sbase + (uint32_t)buf * 16384;
            uint32_t ah[2][4], al[2][4], bb[8][2];
            ldsm4(ah[0], sb + aoff[0]);
            ldsm4(ah[1], sb + aoff[1]);
            ldsm4(al[0], sb + 4096 + aoff[0]);
            ldsm4(al[1], sb + 4096 + aoff[1]);
            #pragma unroll
            for (int p = 0; p < 4; p++) {
                uint32_t r[4];
                ldsm4(r, sb + 8192 + boff[p]);      // W hi
                bb[2 * p][0] = r[0]; bb[2 * p][1] = r[1];
                bb[2 * p + 1][0] = r[2]; bb[2 * p + 1][1] = r[3];
            }
            #pragma unroll
            for (int i = 0; i < 2; i++)
                #pragma unroll
                for (int j = 0; j < 8; j++) {
                    mma16816(d[i][j], ah[i], bb[j]);   // hi*hi
                    mma16816(d[i][j], al[i], bb[j]);   // lo*hi
                }
            #pragma unroll
            for (int p = 0; p < 4; p++) {
                uint32_t r[4];
                ldsm4(r, sb + 12288 + boff[p]);     // W lo
                bb[2 * p][0] = r[0]; bb[2 * p][1] = r[1];
                bb[2 * p + 1][0] = r[2]; bb[2 * p + 1][1] = r[3];
            }
            #pragma unroll
            for (int i = 0; i < 2; i++)
                #pragma unroll
                for (int j = 0; j < 8; j++)
                    mma16816(d[i][j], ah[i], bb[j]);   // hi*lo

            buf  = (buf  == 2) ? 0 : buf + 1;
            nbuf = (nbuf == 2) ? 0 : nbuf + 1;
        }

        // epilogue: bias + tanh -> scatter directly to out[n, idx[n], :]
        float2 bias[8];
        #pragma unroll
        for (int j = 0; j < 8; j++) {
            const int col = block_n + wn * 64 + j * 8 + (lane & 3) * 2;
            bias[j].x = b_in[col] + b_h[col];
            bias[j].y = b_in[col + 1] + b_h[col + 1];
        }
        #pragma unroll
        for (int i = 0; i < 2; i++) {
            const int m0 = block_m + wm * 32 + i * 16 + (lane >> 2);
            const int m1 = m0 + 8;
            const size_t base0 = ((size_t)m0 * LV + (veh_idx[m0] & (LV - 1))) * HD;
            const size_t base1 = ((size_t)m1 * LV + (veh_idx[m1] & (LV - 1))) * HD;
            #pragma unroll
            for (int j = 0; j < 8; j++) {
                const int col = block_n + wn * 64 + j * 8 + (lane & 3) * 2;
                float2 v0, v1;
                v0.x = tanhf(d[i][j][0] + bias[j].x);
                v0.y = tanhf(d[i][j][1] + bias[j].y);
                v1.x = tanhf(d[i][j][2] + bias[j].x);
                v1.y = tanhf(d[i][j][3] + bias[j].y);
                *(float2*)&out[base0 + col] = v0;
                *(float2*)&out[base1 + col] = v1;
            }
        }
    }

    // Copy pool (copy-only CTAs arrive here immediately; no smem used).
    copy_role((const float4*)memory, (float4*)out, veh_idx, lane);
}

extern "C" void kernel_launch(void* const* d_in, const int* in_sizes, int n_in,
                              void* d_out, int out_size)
{
    const float* memory    = (const float*)d_in[0];
    const int*   veh_idx   = (const int*)d_in[1];
    const float* veh_repr  = (const float*)d_in[2];
    const float* cust_repr = (const float*)d_in[3];
    const float* edge_emb  = (const float*)d_in[4];
    const float* W_in      = (const float*)d_in[5];
    const float* b_in      = (const float*)d_in[6];
    const float* W_h       = (const float*)d_in[7];
    const float* b_h       = (const float*)d_in[8];
    float*       out       = (float*)d_out;

    prep_kernel<<<XBLOCKS + WBLOCKS, 256>>>(memory, veh_idx, veh_repr,
                                            cust_repr, edge_emb, W_in, W_h);
    fused_kernel<<<TOTAL_CTAS, 256>>>(memory, veh_idx, b_in, b_h, out);
}